// round 1
// baseline (speedup 1.0000x reference)
#include <cuda_runtime.h>
#include <math.h>

#define BSZ 32
#define TT  2048
#define EP  512
#define AD  512
#define NCH 32
#define FILT 100
#define KW  201

// output layout: c_v (32*512), w (32*2048), h_new (32*512), c_new (32*512)
#define OUT_CV 0
#define OUT_W  (BSZ*EP)            // 16384
#define OUT_H  (OUT_W + BSZ*TT)    // 81920
#define OUT_C  (OUT_H + BSZ*AD)    // 98304

__device__ float g_feat[BSZ*NCH];
__device__ float g_gates[BSZ*4*AD];
__device__ float g_bias[BSZ*AD];
__device__ float g_score[BSZ*TT];
__device__ float g_h[BSZ*AD];

// ---------------------------------------------------------------------------
// K1: location conv (201 taps) + relu + max-pool over T -> feat (B, 32)
// grid (B, NCH), block 256
// ---------------------------------------------------------------------------
__global__ __launch_bounds__(256) void conv_max_kernel(
    const float* __restrict__ att_prev, const float* __restrict__ conv_w)
{
    int b = blockIdx.x, c = blockIdx.y;
    __shared__ float xs[TT];
    __shared__ float ws[KW];
    __shared__ float red[256];
    for (int i = threadIdx.x; i < TT; i += 256) xs[i] = att_prev[b*TT + i];
    for (int i = threadIdx.x; i < KW; i += 256) ws[i] = conv_w[c*KW + i];
    __syncthreads();
    float m = 0.f;  // relu clamps at 0, so init local max to 0
    for (int t = threadIdx.x; t < TT; t += 256) {
        float s = 0.f;
        int k0 = FILT - t;      if (k0 < 0) k0 = 0;
        int k1 = TT + FILT - t; if (k1 > KW) k1 = KW;
        for (int k = k0; k < k1; k++) s += ws[k] * xs[t + k - FILT];
        m = fmaxf(m, s);
    }
    red[threadIdx.x] = m;
    __syncthreads();
    for (int s = 128; s > 0; s >>= 1) {
        if (threadIdx.x < s) red[threadIdx.x] = fmaxf(red[threadIdx.x], red[threadIdx.x + s]);
        __syncthreads();
    }
    if (threadIdx.x == 0) g_feat[b*NCH + c] = red[0];
}

// ---------------------------------------------------------------------------
// K2: LSTM gate pre-activations: gates[b,j] = feat·W_ih[j,:] + att_h·W_hh[j,:] + b
// one warp per j, 4 warps/block, grid 512
// ---------------------------------------------------------------------------
__global__ __launch_bounds__(128) void gates_kernel(
    const float* __restrict__ att_h, const float* __restrict__ W_ih,
    const float* __restrict__ W_hh, const float* __restrict__ b_ih,
    const float* __restrict__ b_hh)
{
    int warp = threadIdx.x >> 5, lane = threadIdx.x & 31;
    int j = blockIdx.x * 4 + warp;   // < 2048
    float wh[16];
    #pragma unroll
    for (int i = 0; i < 16; i++) wh[i] = W_hh[(size_t)j*AD + lane + 32*i];
    float wi = W_ih[j*NCH + lane];
    float bias = b_ih[j] + b_hh[j];
    for (int b = 0; b < BSZ; b++) {
        float s = wi * g_feat[b*NCH + lane];
        #pragma unroll
        for (int i = 0; i < 16; i++) s += wh[i] * att_h[b*AD + lane + 32*i];
        #pragma unroll
        for (int o = 16; o > 0; o >>= 1) s += __shfl_down_sync(0xffffffffu, s, o);
        if (lane == 0) g_gates[b*4*AD + j] = s + bias;
    }
}

// ---------------------------------------------------------------------------
// K2b: LSTM elementwise -> h_new, c_new; also zero the c_v output region
// ---------------------------------------------------------------------------
__global__ __launch_bounds__(256) void lstm_kernel(
    const float* __restrict__ att_c, float* __restrict__ out)
{
    int idx = blockIdx.x * 256 + threadIdx.x;
    if (idx >= BSZ*AD) return;
    int b = idx / AD, a = idx % AD;
    const float* g = g_gates + b*4*AD;
    float gi = g[a], gf = g[AD + a], gg = g[2*AD + a], go = g[3*AD + a];
    float si = 1.f / (1.f + expf(-gi));
    float sf = 1.f / (1.f + expf(-gf));
    float so = 1.f / (1.f + expf(-go));
    float cn = sf * att_c[idx] + si * tanhf(gg);
    float hn = so * tanhf(cn);
    g_h[idx] = hn;
    out[OUT_H + idx] = hn;
    out[OUT_C + idx] = cn;
    out[OUT_CV + idx] = 0.f;   // zero c_v for the atomic reduction in K6
}

// ---------------------------------------------------------------------------
// K3: bias[b,a] = h_new·W_w[:,a] + W_b + dec_z·U_w[:,a] + U_b + V_b
// grid (4, 32), block 128
// ---------------------------------------------------------------------------
__global__ __launch_bounds__(128) void bias_kernel(
    const float* __restrict__ dec_z, const float* __restrict__ W_w,
    const float* __restrict__ W_b, const float* __restrict__ U_w,
    const float* __restrict__ U_b, const float* __restrict__ V_b)
{
    int a = blockIdx.x * 128 + threadIdx.x;
    int b = blockIdx.y;
    __shared__ float hs[AD], zs[AD];
    for (int i = threadIdx.x; i < AD; i += 128) {
        hs[i] = g_h[b*AD + i];
        zs[i] = dec_z[b*AD + i];
    }
    __syncthreads();
    float s = W_b[a] + U_b[a] + V_b[a];
    #pragma unroll 4
    for (int k = 0; k < AD; k++)
        s += hs[k] * W_w[(size_t)k*AD + a] + zs[k] * U_w[(size_t)k*AD + a];
    g_bias[b*AD + a] = s;
}

// ---------------------------------------------------------------------------
// K4: fused score GEMM: score[r] = sum_a g[a]*tanh(enc[r,:]·V[:,a] + bias[b,a]) + gb
// 64x64 tile, 256 threads, 4x4 micro-tile, BK=32. pre is never materialized.
// ---------------------------------------------------------------------------
#define BM 64
#define BN 64
#define BK 32
__global__ __launch_bounds__(256) void score_kernel(
    const float* __restrict__ enc, const float* __restrict__ Vw,
    const float* __restrict__ gw, const float* __restrict__ gb)
{
    int row0 = blockIdx.x * BM;       // flattened b*T + t
    int b = row0 / TT;                // tile lies within one batch (T % BM == 0)
    int tid = threadIdx.x;
    int tx = tid & 15, ty = tid >> 4;

    __shared__ float  As[BK][BM + 1];     // [k][m], padded: conflict-free stores
    __shared__ float4 Bs[BK][BN / 4];     // [k][n/4]
    __shared__ float  red[BM][17];

    float rowsum[4] = {0.f, 0.f, 0.f, 0.f};

    const int mA  = tid >> 2;           // 0..63
    const int kkA = (tid & 3) * 8;      // 0,8,16,24
    const int kB  = tid >> 3;           // 0..31
    const int nB  = (tid & 7) * 8;      // 0..56

    for (int nt = 0; nt < AD / BN; nt++) {
        float acc[4][4];
        #pragma unroll
        for (int i = 0; i < 4; i++)
            #pragma unroll
            for (int j = 0; j < 4; j++) acc[i][j] = 0.f;

        for (int kt = 0; kt < EP / BK; kt++) {
            // A tile: enc rows (64 x 32), stored transposed
            {
                const float4* src = (const float4*)(enc + (size_t)(row0 + mA)*EP + kt*BK + kkA);
                float4 v0 = src[0], v1 = src[1];
                As[kkA + 0][mA] = v0.x; As[kkA + 1][mA] = v0.y;
                As[kkA + 2][mA] = v0.z; As[kkA + 3][mA] = v0.w;
                As[kkA + 4][mA] = v1.x; As[kkA + 5][mA] = v1.y;
                As[kkA + 6][mA] = v1.z; As[kkA + 7][mA] = v1.w;
            }
            // B tile: V_w rows (32 x 64)
            {
                const float4* src = (const float4*)(Vw + (size_t)(kt*BK + kB)*AD + nt*BN + nB);
                Bs[kB][(nB >> 2) + 0] = src[0];
                Bs[kB][(nB >> 2) + 1] = src[1];
            }
            __syncthreads();
            #pragma unroll
            for (int k = 0; k < BK; k++) {
                float a0 = As[k][ty*4 + 0], a1 = As[k][ty*4 + 1];
                float a2 = As[k][ty*4 + 2], a3 = As[k][ty*4 + 3];
                float4 bv = Bs[k][tx];
                acc[0][0] += a0*bv.x; acc[0][1] += a0*bv.y; acc[0][2] += a0*bv.z; acc[0][3] += a0*bv.w;
                acc[1][0] += a1*bv.x; acc[1][1] += a1*bv.y; acc[1][2] += a1*bv.z; acc[1][3] += a1*bv.w;
                acc[2][0] += a2*bv.x; acc[2][1] += a2*bv.y; acc[2][2] += a2*bv.z; acc[2][3] += a2*bv.w;
                acc[3][0] += a3*bv.x; acc[3][1] += a3*bv.y; acc[3][2] += a3*bv.z; acc[3][3] += a3*bv.w;
            }
            __syncthreads();
        }
        // fused epilogue: tanh + weighted sum by g_w
        #pragma unroll
        for (int j = 0; j < 4; j++) {
            int n = nt*BN + tx*4 + j;
            float gv = __ldg(gw + n);
            float bb = g_bias[b*AD + n];
            #pragma unroll
            for (int i = 0; i < 4; i++)
                rowsum[i] += gv * tanhf(acc[i][j] + bb);
        }
    }
    // reduce 16 column-thread partials per row
    #pragma unroll
    for (int i = 0; i < 4; i++) red[ty*4 + i][tx] = rowsum[i];
    __syncthreads();
    if (tid < BM) {
        float s = 0.f;
        #pragma unroll
        for (int x = 0; x < 16; x++) s += red[tid][x];
        g_score[row0 + tid] = s + gb[0];
    }
}

// ---------------------------------------------------------------------------
// K5: masked, scaled softmax over T per batch -> w (written into d_out)
// ---------------------------------------------------------------------------
__global__ __launch_bounds__(256) void softmax_kernel(
    const int* __restrict__ len, float* __restrict__ out)
{
    int b = blockIdx.x;
    int L = len[b];
    __shared__ float red[256];
    float* wout = out + OUT_W + b*TT;

    float mx = -3.0e38f;
    for (int t = threadIdx.x; t < TT; t += 256) {
        float v = (t < L) ? 2.0f * g_score[b*TT + t] : -3.0e38f;
        mx = fmaxf(mx, v);
    }
    red[threadIdx.x] = mx; __syncthreads();
    for (int s = 128; s > 0; s >>= 1) {
        if (threadIdx.x < s) red[threadIdx.x] = fmaxf(red[threadIdx.x], red[threadIdx.x + s]);
        __syncthreads();
    }
    mx = red[0]; __syncthreads();

    float sum = 0.f;
    for (int t = threadIdx.x; t < TT; t += 256) {
        float p = (t < L) ? expf(2.0f * g_score[b*TT + t] - mx) : 0.f;
        wout[t] = p;
        sum += p;
    }
    red[threadIdx.x] = sum; __syncthreads();
    for (int s = 128; s > 0; s >>= 1) {
        if (threadIdx.x < s) red[threadIdx.x] += red[threadIdx.x + s];
        __syncthreads();
    }
    float inv = 1.0f / red[0];
    for (int t = threadIdx.x; t < TT; t += 256) wout[t] *= inv;
}

// ---------------------------------------------------------------------------
// K6: context vector c_v[b,e] = sum_t w[b,t]*enc[b,t,e]  (memory-bound, 134 MB)
// grid (4 e-chunks, 8 t-chunks, 32 b), block 128, atomic partials
// ---------------------------------------------------------------------------
__global__ __launch_bounds__(128) void context_kernel(
    const float* __restrict__ enc, float* __restrict__ out)
{
    int b = blockIdx.z;
    int e = blockIdx.x * 128 + threadIdx.x;
    int t0 = blockIdx.y * 256;
    const float* wrow = out + OUT_W + b*TT + t0;
    const float* ep = enc + ((size_t)b*TT + t0)*EP + e;
    float s = 0.f;
    #pragma unroll 4
    for (int t = 0; t < 256; t++) s += wrow[t] * ep[(size_t)t * EP];
    atomicAdd(&out[OUT_CV + b*EP + e], s);
}

// ---------------------------------------------------------------------------
extern "C" void kernel_launch(void* const* d_in, const int* in_sizes, int n_in,
                              void* d_out, int out_size)
{
    const float* enc      = (const float*)d_in[0];   // (32,2048,512)
    const int*   enc_len  = (const int*)  d_in[1];   // (32,)
    const float* dec_z    = (const float*)d_in[2];   // (32,512)
    const float* att_prev = (const float*)d_in[3];   // (32,2048)
    const float* att_h    = (const float*)d_in[4];   // (32,512)
    const float* att_c    = (const float*)d_in[5];   // (32,512)
    const float* W_w      = (const float*)d_in[6];   // (512,512)
    const float* W_b      = (const float*)d_in[7];   // (512,)
    const float* V_w      = (const float*)d_in[8];   // (512,512)
    const float* V_b      = (const float*)d_in[9];   // (512,)
    const float* U_w      = (const float*)d_in[10];  // (512,512)
    const float* U_b      = (const float*)d_in[11];  // (512,)
    const float* g_w      = (const float*)d_in[12];  // (512,1)
    const float* g_b      = (const float*)d_in[13];  // (1,)
    const float* conv_w   = (const float*)d_in[14];  // (32,1,201)
    const float* W_ih     = (const float*)d_in[15];  // (2048,32)
    const float* W_hh     = (const float*)d_in[16];  // (2048,512)
    const float* b_ih     = (const float*)d_in[17];  // (2048,)
    const float* b_hh     = (const float*)d_in[18];  // (2048,)
    float* out = (float*)d_out;

    // K1: conv + relu + maxpool
    conv_max_kernel<<<dim3(BSZ, NCH), 256>>>(att_prev, conv_w);
    // K2: LSTM gates
    gates_kernel<<<512, 128>>>(att_h, W_ih, W_hh, b_ih, b_hh);
    // K2b: LSTM cell elementwise (+ zero c_v)
    lstm_kernel<<<(BSZ*AD + 255) / 256, 256>>>(att_c, out);
    // K3: per-batch additive bias (wh + dec_proj + V_b)
    bias_kernel<<<dim3(4, BSZ), 128>>>(dec_z, W_w, W_b, U_w, U_b, V_b);
    // K4: fused GEMM + tanh + g-dot -> score
    score_kernel<<<(BSZ*TT) / BM, 256>>>(enc, V_w, g_w, g_b);
    // K5: masked scaled softmax -> w
    softmax_kernel<<<BSZ, 256>>>(enc_len, out);
    // K6: context vector
    context_kernel<<<dim3(4, 8, BSZ), 128>>>(enc, out);
}

// round 3
// speedup vs baseline: 2.1841x; 2.1841x over previous
#include <cuda_runtime.h>
#include <cuda_bf16.h>
#include <cstdint>
#include <math.h>

#define BSZ 32
#define TT  2048
#define EP  512
#define AD  512
#define NCH 32
#define FILT 100
#define KW  201

// output layout: c_v (32*512), w (32*2048), h_new (32*512), c_new (32*512)
#define OUT_CV 0
#define OUT_W  (BSZ*EP)            // 16384
#define OUT_H  (OUT_W + BSZ*TT)    // 81920
#define OUT_C  (OUT_H + BSZ*AD)    // 98304

__device__ float g_feat[BSZ*NCH];
__device__ float g_gates[BSZ*4*AD];
__device__ float g_bias[BSZ*AD];
__device__ float g_score[BSZ*TT];
__device__ float g_h[BSZ*AD];

// split-bf16 operands: A = enc rows, layout (B*T, 1024): cols [0,512)=hi, [512,1024)=lo
__device__ __nv_bfloat16 g_Abf[(size_t)BSZ*TT*1024];
// B = V_w^T, layout (512 n-rows, 1024): cols [0,512)=hi(V_w[k][n]), [512,1024)=lo
__device__ __nv_bfloat16 g_Bcat[(size_t)AD*1024];

// ===========================================================================
// helpers
// ===========================================================================
__device__ __forceinline__ uint32_t smem_to_u32(const void* p) {
    uint32_t a;
    asm("{ .reg .u64 t; cvta.to.shared.u64 t, %1; cvt.u32.u64 %0, t; }" : "=r"(a) : "l"(p));
    return a;
}
__device__ __forceinline__ void cp_async16(uint32_t dst, const void* src) {
    asm volatile("cp.async.cg.shared.global [%0], [%1], 16;" :: "r"(dst), "l"(src));
}
__device__ __forceinline__ void cp_commit() {
    asm volatile("cp.async.commit_group;" ::: "memory");
}
__device__ __forceinline__ void ldsm4(uint32_t r[4], uint32_t addr) {
    asm volatile("ldmatrix.sync.aligned.m8n8.x4.shared.b16 {%0,%1,%2,%3}, [%4];"
        : "=r"(r[0]), "=r"(r[1]), "=r"(r[2]), "=r"(r[3]) : "r"(addr));
}
__device__ __forceinline__ void mma16816(float d[4], const uint32_t a[4],
                                         uint32_t b0, uint32_t b1) {
    asm volatile("mma.sync.aligned.m16n8k16.row.col.f32.bf16.bf16.f32 "
        "{%0,%1,%2,%3}, {%4,%5,%6,%7}, {%8,%9}, {%0,%1,%2,%3};"
        : "+f"(d[0]), "+f"(d[1]), "+f"(d[2]), "+f"(d[3])
        : "r"(a[0]), "r"(a[1]), "r"(a[2]), "r"(a[3]), "r"(b0), "r"(b1));
}

// FMA-only tanh: exp2 poly + bit-ldexp + magic-seed Newton reciprocal.
// abs err < ~1e-5; no MUFU (MUFU chip throughput is only 74/cyc).
__device__ __forceinline__ float fast_tanh(float x) {
    float ax = fminf(fabsf(x), 9.0f);
    float y = ax * 2.885390082f;                 // 2x * log2(e)
    float n = rintf(y);
    float f = y - n;
    float p = 1.3333558e-3f;
    p = fmaf(p, f, 9.6181291e-3f);
    p = fmaf(p, f, 5.5504109e-2f);
    p = fmaf(p, f, 2.4022651e-1f);
    p = fmaf(p, f, 6.9314718e-1f);
    p = fmaf(p, f, 1.0f);
    float z = __int_as_float(__float_as_int(p) + ((int)n << 23));   // e^{2ax}
    float d = z + 1.0f;
    float r = __int_as_float(0x7EF311C3u - __float_as_uint(d));     // ~1/d
    r = r * (2.0f - d * r);
    r = r * (2.0f - d * r);
    float t = (z - 1.0f) * r;
    return __int_as_float(__float_as_int(t) | (__float_as_int(x) & 0x80000000));
}

// ===========================================================================
// K0a: convert enc -> [hi|lo] bf16 rows; also zero g_score
// ===========================================================================
__global__ __launch_bounds__(256) void convA_kernel(const float* __restrict__ enc)
{
    int i4 = blockIdx.x * 256 + threadIdx.x;        // 8,388,608 threads
    if (i4 < BSZ*TT) g_score[i4] = 0.f;
    size_t base = (size_t)i4 * 4;
    int row = (int)(base >> 9);
    int k0  = (int)(base & 511);
    float4 v = *reinterpret_cast<const float4*>(enc + base);
    __nv_bfloat16 h0 = __float2bfloat16(v.x), h1 = __float2bfloat16(v.y);
    __nv_bfloat16 h2 = __float2bfloat16(v.z), h3 = __float2bfloat16(v.w);
    __nv_bfloat16 l0 = __float2bfloat16(v.x - __bfloat162float(h0));
    __nv_bfloat16 l1 = __float2bfloat16(v.y - __bfloat162float(h1));
    __nv_bfloat16 l2 = __float2bfloat16(v.z - __bfloat162float(h2));
    __nv_bfloat16 l3 = __float2bfloat16(v.w - __bfloat162float(h3));
    __nv_bfloat162* dh = reinterpret_cast<__nv_bfloat162*>(g_Abf + (size_t)row*1024 + k0);
    __nv_bfloat162* dl = reinterpret_cast<__nv_bfloat162*>(g_Abf + (size_t)row*1024 + 512 + k0);
    dh[0] = __nv_bfloat162(h0, h1); dh[1] = __nv_bfloat162(h2, h3);
    dl[0] = __nv_bfloat162(l0, l1); dl[1] = __nv_bfloat162(l2, l3);
}

// K0b: convert + transpose V_w -> Bcat (n-major, [hi|lo])
__global__ __launch_bounds__(256) void convB_kernel(const float* __restrict__ Vw)
{
    int idx = blockIdx.x * 256 + threadIdx.x;       // 262144
    int k = idx >> 9, n = idx & 511;
    float x = Vw[idx];
    __nv_bfloat16 h = __float2bfloat16(x);
    __nv_bfloat16 l = __float2bfloat16(x - __bfloat162float(h));
    g_Bcat[(size_t)n*1024 + k]       = h;
    g_Bcat[(size_t)n*1024 + 512 + k] = l;
}

// ===========================================================================
// K1: location conv (201 taps) + relu + max-pool over T -> feat (B, 32)
// ===========================================================================
__global__ __launch_bounds__(256) void conv_max_kernel(
    const float* __restrict__ att_prev, const float* __restrict__ conv_w)
{
    int b = blockIdx.x, c = blockIdx.y;
    __shared__ float xs[TT];
    __shared__ float ws[KW];
    __shared__ float red[256];
    for (int i = threadIdx.x; i < TT; i += 256) xs[i] = att_prev[b*TT + i];
    for (int i = threadIdx.x; i < KW; i += 256) ws[i] = conv_w[c*KW + i];
    __syncthreads();
    float m = 0.f;
    for (int t = threadIdx.x; t < TT; t += 256) {
        float s = 0.f;
        int k0 = FILT - t;      if (k0 < 0) k0 = 0;
        int k1 = TT + FILT - t; if (k1 > KW) k1 = KW;
        for (int k = k0; k < k1; k++) s += ws[k] * xs[t + k - FILT];
        m = fmaxf(m, s);
    }
    red[threadIdx.x] = m;
    __syncthreads();
    for (int s = 128; s > 0; s >>= 1) {
        if (threadIdx.x < s) red[threadIdx.x] = fmaxf(red[threadIdx.x], red[threadIdx.x + s]);
        __syncthreads();
    }
    if (threadIdx.x == 0) g_feat[b*NCH + c] = red[0];
}

// ===========================================================================
// K2: LSTM gate pre-activations
// ===========================================================================
__global__ __launch_bounds__(128) void gates_kernel(
    const float* __restrict__ att_h, const float* __restrict__ W_ih,
    const float* __restrict__ W_hh, const float* __restrict__ b_ih,
    const float* __restrict__ b_hh)
{
    int warp = threadIdx.x >> 5, lane = threadIdx.x & 31;
    int j = blockIdx.x * 4 + warp;
    float wh[16];
    #pragma unroll
    for (int i = 0; i < 16; i++) wh[i] = W_hh[(size_t)j*AD + lane + 32*i];
    float wi = W_ih[j*NCH + lane];
    float bias = b_ih[j] + b_hh[j];
    for (int b = 0; b < BSZ; b++) {
        float s = wi * g_feat[b*NCH + lane];
        #pragma unroll
        for (int i = 0; i < 16; i++) s += wh[i] * att_h[b*AD + lane + 32*i];
        #pragma unroll
        for (int o = 16; o > 0; o >>= 1) s += __shfl_down_sync(0xffffffffu, s, o);
        if (lane == 0) g_gates[b*4*AD + j] = s + bias;
    }
}

// ===========================================================================
// K2b: LSTM elementwise -> h_new, c_new; init c_v=0 and g_bias=const
// ===========================================================================
__global__ __launch_bounds__(256) void lstm_kernel(
    const float* __restrict__ att_c, float* __restrict__ out,
    const float* __restrict__ W_b, const float* __restrict__ U_b,
    const float* __restrict__ V_b)
{
    int idx = blockIdx.x * 256 + threadIdx.x;
    if (idx >= BSZ*AD) return;
    int b = idx / AD, a = idx % AD;
    const float* g = g_gates + b*4*AD;
    float gi = g[a], gf = g[AD + a], gg = g[2*AD + a], go = g[3*AD + a];
    float si = 1.f / (1.f + expf(-gi));
    float sf = 1.f / (1.f + expf(-gf));
    float so = 1.f / (1.f + expf(-go));
    float cn = sf * att_c[idx] + si * tanhf(gg);
    float hn = so * tanhf(cn);
    g_h[idx] = hn;
    out[OUT_H + idx] = hn;
    out[OUT_C + idx] = cn;
    out[OUT_CV + idx] = 0.f;
    g_bias[idx] = W_b[a] + U_b[a] + V_b[a];   // bias_kernel atomically adds on top
}

// ===========================================================================
// K3: bias[b,a] += h_new·W_w[:,a] + dec_z·U_w[:,a]  (k-split, atomic)
// ===========================================================================
__global__ __launch_bounds__(128) void bias_kernel(
    const float* __restrict__ dec_z, const float* __restrict__ W_w,
    const float* __restrict__ U_w)
{
    int a  = blockIdx.x * 128 + threadIdx.x;
    int b  = blockIdx.y;
    int k0 = blockIdx.z * 128;
    __shared__ float hs[128], zs[128];
    hs[threadIdx.x] = g_h[b*AD + k0 + threadIdx.x];
    zs[threadIdx.x] = dec_z[b*AD + k0 + threadIdx.x];
    __syncthreads();
    float s = 0.f;
    #pragma unroll 8
    for (int k = 0; k < 128; k++)
        s += hs[k] * W_w[(size_t)(k0 + k)*AD + a] + zs[k] * U_w[(size_t)(k0 + k)*AD + a];
    atomicAdd(&g_bias[b*AD + a], s);
}

// ===========================================================================
// K4: mma.sync split-bf16 score GEMM + fused tanh/g-dot epilogue.
// CTA tile 128(M)x128(N); per k-chunk (BK=32) load {Ah,Al,Bh,Bl} once,
// run 3 MMA passes: Ah*Bh + Al*Bh + Ah*Bl. Double-buffered cp.async.
// 8 warps arranged 2(M)x4(N): warp tile 64x32. mma.m16n8k16 bf16.
// ===========================================================================
#define ASTR 40                      // bf16 elems per smem row (80B, 16B-aligned, conflict-free ldmatrix)
#define CHUNK_B (128*ASTR*2)         // 10240 bytes per 128x32 chunk
#define SCORE_SMEM (8*CHUNK_B)       // 2 sets x 4 chunks = 81920 B

__device__ __forceinline__ void compute_pass(
    uint32_t aBase, uint32_t bBase, int warp_m, int warp_n, int lane,
    float (&acc)[4][4][4])
{
    int rsel = lane & 15, csel = (lane >> 4) * 8;
    #pragma unroll
    for (int ks = 0; ks < 2; ks++) {
        uint32_t a[4][4], bq[2][4];
        #pragma unroll
        for (int mt = 0; mt < 4; mt++) {
            uint32_t addr = aBase + ((warp_m*64 + mt*16 + rsel)*ASTR + csel + ks*16)*2;
            ldsm4(a[mt], addr);
        }
        #pragma unroll
        for (int np = 0; np < 2; np++) {
            uint32_t addr = bBase + ((warp_n*32 + np*16 + rsel)*ASTR + csel + ks*16)*2;
            ldsm4(bq[np], addr);
        }
        #pragma unroll
        for (int mt = 0; mt < 4; mt++)
            #pragma unroll
            for (int nt = 0; nt < 4; nt++)
                mma16816(acc[mt][nt], a[mt], bq[nt>>1][nt&1], bq[nt>>1][2+(nt&1)]);
    }
}

__global__ __launch_bounds__(256, 2) void score_mma_kernel(const float* __restrict__ gw)
{
    extern __shared__ char smem[];
    uint32_t smem_base = smem_to_u32(smem);
    int tid = threadIdx.x, lane = tid & 31, wid = tid >> 5;
    int mtile = blockIdx.x >> 2, ntile = blockIdx.x & 3;   // 4 n-tiles adjacent: A reuse in L2
    int row0 = mtile * 128, n0 = ntile * 128;
    int b = row0 / TT;
    int warp_m = wid & 1, warp_n = wid >> 1;

    float acc[4][4][4];
    #pragma unroll
    for (int mt = 0; mt < 4; mt++)
        #pragma unroll
        for (int nt = 0; nt < 4; nt++)
            #pragma unroll
            for (int i = 0; i < 4; i++) acc[mt][nt][i] = 0.f;

    const __nv_bfloat16* Arow = g_Abf + (size_t)row0 * 1024;
    const __nv_bfloat16* Brow = g_Bcat + (size_t)n0 * 1024;

    // per-thread piece indices for cp.async (2 pieces per chunk)
    int r0p = (tid + 0)   >> 2, q0p = (tid + 0)   & 3;
    int r1p = (tid + 256) >> 2, q1p = (tid + 256) & 3;

    auto load_set = [&](int s, int kc) {
        const __nv_bfloat16* src[4] = {
            Arow + kc*32,            // Ah
            Arow + 512 + kc*32,      // Al
            Brow + kc*32,            // Bh
            Brow + 512 + kc*32 };    // Bl
        #pragma unroll
        for (int c = 0; c < 4; c++) {
            uint32_t dstb = smem_base + (uint32_t)(s*4 + c) * CHUNK_B;
            cp_async16(dstb + (r0p*ASTR + q0p*8)*2, src[c] + (size_t)r0p*1024 + q0p*8);
            cp_async16(dstb + (r1p*ASTR + q1p*8)*2, src[c] + (size_t)r1p*1024 + q1p*8);
        }
        cp_commit();
    };

    load_set(0, 0);
    for (int kc = 0; kc < 16; kc++) {
        if (kc + 1 < 16) {
            load_set((kc + 1) & 1, kc + 1);
            asm volatile("cp.async.wait_group 1;" ::: "memory");
        } else {
            asm volatile("cp.async.wait_group 0;" ::: "memory");
        }
        __syncthreads();
        int s = kc & 1;
        uint32_t Ah = smem_base + (uint32_t)(s*4 + 0) * CHUNK_B;
        uint32_t Al = smem_base + (uint32_t)(s*4 + 1) * CHUNK_B;
        uint32_t Bh = smem_base + (uint32_t)(s*4 + 2) * CHUNK_B;
        uint32_t Bl = smem_base + (uint32_t)(s*4 + 3) * CHUNK_B;
        compute_pass(Ah, Bh, warp_m, warp_n, lane, acc);
        compute_pass(Al, Bh, warp_m, warp_n, lane, acc);
        compute_pass(Ah, Bl, warp_m, warp_n, lane, acc);
        __syncthreads();
    }

    // epilogue: rowsum += g[n]*tanh(acc + bias[b,n]); reduce over 4 q-lanes; atomic
    int g = lane >> 2, q = lane & 3;
    float gv[8], bb[8];
    #pragma unroll
    for (int nt = 0; nt < 4; nt++)
        #pragma unroll
        for (int h = 0; h < 2; h++) {
            int n = n0 + warp_n*32 + nt*8 + q*2 + h;
            gv[nt*2 + h] = __ldg(gw + n);
            bb[nt*2 + h] = g_bias[b*AD + n];
        }
    #pragma unroll
    for (int mt = 0; mt < 4; mt++) {
        float p0 = 0.f, p1 = 0.f;
        #pragma unroll
        for (int nt = 0; nt < 4; nt++) {
            p0 += gv[nt*2+0] * fast_tanh(acc[mt][nt][0] + bb[nt*2+0]);
            p0 += gv[nt*2+1] * fast_tanh(acc[mt][nt][1] + bb[nt*2+1]);
            p1 += gv[nt*2+0] * fast_tanh(acc[mt][nt][2] + bb[nt*2+0]);
            p1 += gv[nt*2+1] * fast_tanh(acc[mt][nt][3] + bb[nt*2+1]);
        }
        p0 += __shfl_xor_sync(0xffffffffu, p0, 1);
        p0 += __shfl_xor_sync(0xffffffffu, p0, 2);
        p1 += __shfl_xor_sync(0xffffffffu, p1, 1);
        p1 += __shfl_xor_sync(0xffffffffu, p1, 2);
        if (q == 0) {
            atomicAdd(&g_score[row0 + warp_m*64 + mt*16 + g],     p0);
            atomicAdd(&g_score[row0 + warp_m*64 + mt*16 + 8 + g], p1);
        }
    }
}

// ===========================================================================
// K5: masked, scaled softmax over T per batch -> w (g_b dropped: shift-invariant)
// ===========================================================================
__global__ __launch_bounds__(256) void softmax_kernel(
    const int* __restrict__ len, float* __restrict__ out)
{
    int b = blockIdx.x;
    int L = len[b];
    __shared__ float red[256];
    float* wout = out + OUT_W + b*TT;

    float mx = -3.0e38f;
    for (int t = threadIdx.x; t < TT; t += 256) {
        float v = (t < L) ? 2.0f * g_score[b*TT + t] : -3.0e38f;
        mx = fmaxf(mx, v);
    }
    red[threadIdx.x] = mx; __syncthreads();
    for (int s = 128; s > 0; s >>= 1) {
        if (threadIdx.x < s) red[threadIdx.x] = fmaxf(red[threadIdx.x], red[threadIdx.x + s]);
        __syncthreads();
    }
    mx = red[0]; __syncthreads();

    float sum = 0.f;
    for (int t = threadIdx.x; t < TT; t += 256) {
        float p = (t < L) ? expf(2.0f * g_score[b*TT + t] - mx) : 0.f;
        wout[t] = p;
        sum += p;
    }
    red[threadIdx.x] = sum; __syncthreads();
    for (int s = 128; s > 0; s >>= 1) {
        if (threadIdx.x < s) red[threadIdx.x] += red[threadIdx.x + s];
        __syncthreads();
    }
    float inv = 1.0f / red[0];
    for (int t = threadIdx.x; t < TT; t += 256) wout[t] *= inv;
}

// ===========================================================================
// K6: context vector c_v[b,e] = sum_t w[b,t]*enc[b,t,e]
// ===========================================================================
__global__ __launch_bounds__(128) void context_kernel(
    const float* __restrict__ enc, float* __restrict__ out)
{
    int b = blockIdx.z;
    int e = blockIdx.x * 128 + threadIdx.x;
    int t0 = blockIdx.y * 256;
    const float* wrow = out + OUT_W + b*TT + t0;
    const float* ep = enc + ((size_t)b*TT + t0)*EP + e;
    float s = 0.f;
    #pragma unroll 4
    for (int t = 0; t < 256; t++) s += wrow[t] * ep[(size_t)t * EP];
    atomicAdd(&out[OUT_CV + b*EP + e], s);
}

// ===========================================================================
extern "C" void kernel_launch(void* const* d_in, const int* in_sizes, int n_in,
                              void* d_out, int out_size)
{
    const float* enc      = (const float*)d_in[0];
    const int*   enc_len  = (const int*)  d_in[1];
    const float* dec_z    = (const float*)d_in[2];
    const float* att_prev = (const float*)d_in[3];
    const float* att_h    = (const float*)d_in[4];
    const float* att_c    = (const float*)d_in[5];
    const float* W_w      = (const float*)d_in[6];
    const float* W_b      = (const float*)d_in[7];
    const float* V_w      = (const float*)d_in[8];
    const float* V_b      = (const float*)d_in[9];
    const float* U_w      = (const float*)d_in[10];
    const float* U_b      = (const float*)d_in[11];
    const float* g_w      = (const float*)d_in[12];
    const float* g_b      = (const float*)d_in[13];  // unused: softmax shift-invariant
    const float* conv_w   = (const float*)d_in[14];
    const float* W_ih     = (const float*)d_in[15];
    const float* W_hh     = (const float*)d_in[16];
    const float* b_ih     = (const float*)d_in[17];
    const float* b_hh     = (const float*)d_in[18];
    float* out = (float*)d_out;
    (void)g_b;

    cudaFuncSetAttribute(score_mma_kernel, cudaFuncAttributeMaxDynamicSharedMemorySize, SCORE_SMEM);

    // K0: bf16 hi/lo conversion (also zeroes g_score)
    convA_kernel<<<(BSZ*TT*EP/4 + 255) / 256, 256>>>(enc);
    convB_kernel<<<(EP*AD + 255) / 256, 256>>>(V_w);
    // K1: conv + relu + maxpool
    conv_max_kernel<<<dim3(BSZ, NCH), 256>>>(att_prev, conv_w);
    // K2: LSTM gates
    gates_kernel<<<512, 128>>>(att_h, W_ih, W_hh, b_ih, b_hh);
    // K2b: LSTM cell elementwise (+ zero c_v, init g_bias const)
    lstm_kernel<<<(BSZ*AD + 255) / 256, 256>>>(att_c, out, W_b, U_b, V_b);
    // K3: per-batch additive bias (wh + dec_proj), k-split atomic
    bias_kernel<<<dim3(4, BSZ, 4), 128>>>(dec_z, W_w, U_w);
    // K4: mma.sync split-bf16 GEMM + tanh/g-dot -> score (atomic partials)
    score_mma_kernel<<<(BSZ*TT/128) * 4, 256, SCORE_SMEM>>>(g_w);
    // K5: masked scaled softmax -> w
    softmax_kernel<<<BSZ, 256>>>(enc_len, out);
    // K6: context vector
    context_kernel<<<dim3(4, 8, BSZ), 128>>>(enc, out);
}